// round 14
// baseline (speedup 1.0000x reference)
#include <cuda_runtime.h>
#include <cuda_fp16.h>
#include <cuda_bf16.h>

#define NN 50000
#define EE 600000
#define ET (EE + NN)   // edges incl. self loops
#define HH 128
#define NEG 0.2f

// ---------------- device scratch (no allocs allowed) ----------------
__device__ uint2  g_hp16[NN * 32];    // h @ W^T in fp16 (4 vals per uint2)
__device__ uint2  g_a16[NN * 32];     // GEMM A operand in fp16 (x, then layer-1 out)
__device__ uint2  g_w16[2][4096];     // W0/W1 in fp16 ([c][k] row-major)
__device__ float  g_s[NN];            // hp . att_src
__device__ float  g_d[NN];            // hp . att_dst
__device__ int    g_cnt[NN];          // degree counts, then scatter cursors
__device__ int    g_off[NN + 1];      // CSR offsets by destination
__device__ uint2  g_epack[ET];        // CSR slot: {src, bitcast(edge_attr)}
__device__ float  g_scal[4];          // [0]=mean(edge_attr) [1]=c0 [2]=c1
__device__ float  g_partial[256];     // mean reduction partials
__device__ int    g_blksum[256];      // scan block partials

// ---------------- helpers ----------------
__device__ __forceinline__ unsigned packh2(float a, float b) {
    __half2 h = __floats2half2_rn(a, b);
    return *reinterpret_cast<unsigned*>(&h);
}

__device__ __forceinline__ void mma_f16(float* c, const unsigned* a,
                                        unsigned b0, unsigned b1) {
    asm volatile(
        "mma.sync.aligned.m16n8k16.row.col.f32.f16.f16.f32 "
        "{%0,%1,%2,%3}, {%4,%5,%6,%7}, {%8,%9}, {%0,%1,%2,%3};"
        : "+f"(c[0]), "+f"(c[1]), "+f"(c[2]), "+f"(c[3])
        : "r"(a[0]), "r"(a[1]), "r"(a[2]), "r"(a[3]), "r"(b0), "r"(b1));
}

__device__ __forceinline__ void ldsm4(unsigned& a0, unsigned& a1,
                                      unsigned& a2, unsigned& a3, unsigned addr) {
    asm volatile("ldmatrix.sync.aligned.m8n8.x4.shared.b16 {%0,%1,%2,%3}, [%4];"
                 : "=r"(a0), "=r"(a1), "=r"(a2), "=r"(a3) : "r"(addr));
}

__device__ __forceinline__ void ldsm2(unsigned& a0, unsigned& a1, unsigned addr) {
    asm volatile("ldmatrix.sync.aligned.m8n8.x2.shared.b16 {%0,%1}, [%2];"
                 : "=r"(a0), "=r"(a1) : "r"(addr));
}

// ---------------- conv: x -> out cols 0..127 + fp16 A; W0/W1 -> fp16 ----------
#define NB_X ((NN * 32) / 256)          // 6250
__global__ void conv_k(const float4* __restrict__ x4, float* __restrict__ out,
                       const float4* __restrict__ W0_4,
                       const float4* __restrict__ W1_4) {
    int bid = blockIdx.x;
    if (bid < NB_X) {
        int i = bid * 256 + threadIdx.x;
        float4 v = x4[i];
        int n = i >> 5, q = i & 31;
        *(float4*)&out[n * 384 + q * 4] = v;
        g_a16[i] = make_uint2(packh2(v.x, v.y), packh2(v.z, v.w));
    } else {
        int j = (bid - NB_X) * 256 + threadIdx.x;
        int mat = j >> 12, idx = j & 4095;
        float4 v = mat ? W1_4[idx] : W0_4[idx];
        g_w16[mat][idx] = make_uint2(packh2(v.x, v.y), packh2(v.z, v.w));
    }
}

// ---------------- CSR pre: cnt init + mean partials ---------------------------
__global__ void pre_csr_k(const float* __restrict__ ea) {
    int bid = blockIdx.x;
    int t = threadIdx.x;
    if (bid < 196) {
        int i = bid * 256 + t;
        if (i < NN) g_cnt[i] = 1;            // self loop pre-counted
    } else {
        __shared__ float sm[256];
        int mb = bid - 196;
        float sum = 0.f;
        for (int i = mb * 256 + t; i < EE; i += 256 * 256) sum += ea[i];
        sm[t] = sum;
        __syncthreads();
        for (int o = 128; o; o >>= 1) {
            if (t < o) sm[t] += sm[t + o];
            __syncthreads();
        }
        if (t == 0) g_partial[mb] = sm[0];
    }
}

// ---------------- fused: degree count + scalar setup --------------------------
#define NB_CNT ((EE / 4 + 255) / 256)   // 586
__global__ void count_setup_k(const int* __restrict__ ei,
                              const float* __restrict__ We0,
                              const float* __restrict__ ae0,
                              const float* __restrict__ We1,
                              const float* __restrict__ ae1) {
    if (blockIdx.x < NB_CNT) {
        int e4 = (blockIdx.x * 256 + threadIdx.x) * 4;
        if (e4 >= EE) return;
        int4 d = *(const int4*)&ei[EE + e4];    // EE % 4 == 0
        atomicAdd(&g_cnt[d.x], 1);
        atomicAdd(&g_cnt[d.y], 1);
        atomicAdd(&g_cnt[d.z], 1);
        atomicAdd(&g_cnt[d.w], 1);
    } else {
        __shared__ float sm[256];
        int t = threadIdx.x;
        sm[t] = g_partial[t];
        __syncthreads();
        for (int o = 128; o; o >>= 1) {
            if (t < o) sm[t] += sm[t + o];
            __syncthreads();
        }
        if (t == 0) g_scal[0] = sm[0] / (float)EE;
        __syncthreads();
        sm[t] = (t < HH) ? We0[t] * ae0[t] : 0.f;
        __syncthreads();
        for (int o = 128; o; o >>= 1) {
            if (t < o) sm[t] += sm[t + o];
            __syncthreads();
        }
        if (t == 0) g_scal[1] = sm[0];
        __syncthreads();
        sm[t] = (t < HH) ? We1[t] * ae1[t] : 0.f;
        __syncthreads();
        for (int o = 128; o; o >>= 1) {
            if (t < o) sm[t] += sm[t + o];
            __syncthreads();
        }
        if (t == 0) g_scal[2] = sm[0];
    }
}

// ---------------- scan ----------------
__global__ void scan1_k() {
    __shared__ int sm[256];
    int t = threadIdx.x;
    int gi = blockIdx.x * 256 + t;
    int v = (gi < NN) ? g_cnt[gi] : 0;
    sm[t] = v;
    __syncthreads();
    for (int o = 1; o < 256; o <<= 1) {
        int add = (t >= o) ? sm[t - o] : 0;
        __syncthreads();
        sm[t] += add;
        __syncthreads();
    }
    if (gi < NN) g_off[gi] = sm[t] - v;
    if (t == 255) g_blksum[blockIdx.x] = sm[255];
}

// per-block: base = sum of blksum[0..bid-1], then apply
__global__ void scan3_k() {
    __shared__ int sm[256];
    int t = threadIdx.x;
    sm[t] = (t < (int)blockIdx.x) ? g_blksum[t] : 0;
    __syncthreads();
    for (int o = 128; o; o >>= 1) {
        if (t < o) sm[t] += sm[t + o];
        __syncthreads();
    }
    int base = sm[0];
    int gi = blockIdx.x * 256 + t;
    if (gi < NN) {
        int off = g_off[gi] + base;
        g_off[gi] = off;
        g_cnt[gi] = off;
    }
    if (gi == 0) g_off[NN] = ET;
}

__global__ void scatter_k(const int* __restrict__ ei,
                          const float* __restrict__ eattr) {
    int t = blockIdx.x * blockDim.x + threadIdx.x;
    int e2 = t * 2;
    if (e2 < EE) {                           // EE % 2 == 0
        int2 s = *(const int2*)&ei[e2];
        int2 d = *(const int2*)&ei[EE + e2];
        float2 a = *(const float2*)&eattr[e2];
        int p0 = atomicAdd(&g_cnt[d.x], 1);
        g_epack[p0] = make_uint2((unsigned)s.x, __float_as_uint(a.x));
        int p1 = atomicAdd(&g_cnt[d.y], 1);
        g_epack[p1] = make_uint2((unsigned)s.y, __float_as_uint(a.y));
    } else {
        int n = e2 - EE;                     // self loops: 2 per thread
        #pragma unroll
        for (int q = 0; q < 2; q++, n++) {
            if (n < NN) {
                int pos = atomicAdd(&g_cnt[n], 1);
                g_epack[pos] = make_uint2((unsigned)n, __float_as_uint(g_scal[0]));
            }
        }
    }
}

// ---------------- fp16 GEMM: 1 tile/block, 3 CTAs/SM (single wave) ------------
#define ROWB 272
#define TILEB (128 * ROWB)
#define SMEM_GEMM (2 * TILEB + 512 * 4 + 256 * 4)
__global__ __launch_bounds__(256, 3) void gemm_tc_k(
    int layer, const float* __restrict__ as, const float* __restrict__ ad) {
    extern __shared__ char smem[];
    unsigned sW = (unsigned)__cvta_generic_to_shared(smem);
    unsigned sA = sW + TILEB;
    unsigned* Cs = (unsigned*)(smem + TILEB);          // C reuses A buffer
    float* red = (float*)(smem + 2 * TILEB);           // 512 floats
    float* sAS = red + 512;                            // 128 floats
    float* sAD = sAS + 128;                            // 128 floats

    const __half* __restrict__ A16 = (const __half*)g_a16;
    const __half* __restrict__ W16 = (const __half*)g_w16[layer];

    int tid = threadIdx.x;
    int wid = tid >> 5, lane = tid & 31;
    int warp_m = wid >> 1;
    int warp_n = wid & 1;
    int g = lane >> 2;
    int tg = lane & 3;
    int row_blk = blockIdx.x * 128;

    for (int i = tid; i < 2048; i += 256) {
        int r = i >> 4, cc = i & 15;
        asm volatile("cp.async.ca.shared.global [%0], [%1], 16, 16;"
                     :: "r"(sW + r * ROWB + cc * 16),
                        "l"(W16 + r * 128 + cc * 8));
    }
    for (int i = tid; i < 2048; i += 256) {
        int r = i >> 4, cc = i & 15;
        int gr = row_blk + r;
        const __half* src = A16 + (size_t)(gr < NN ? gr : 0) * 128 + cc * 8;
        int sz = (gr < NN) ? 16 : 0;
        asm volatile("cp.async.ca.shared.global [%0], [%1], 16, %2;"
                     :: "r"(sA + r * ROWB + cc * 16), "l"(src), "r"(sz));
    }
    asm volatile("cp.async.commit_group;");
    if (tid < 128) sAS[tid] = as[tid];
    else           sAD[tid - 128] = ad[tid - 128];
    asm volatile("cp.async.wait_group 0;");
    __syncthreads();

    int sel = lane >> 3, lrow = lane & 7;
    int arow0 = warp_m * 32 + lrow + ((sel & 1) ? 8 : 0);
    unsigned aaddr0 = sA + arow0 * ROWB + ((sel & 2) ? 16 : 0);
    unsigned baddr0 = sW + (warp_n * 64 + (lane & 7)) * ROWB + ((sel & 1) ? 16 : 0);

    float c[2][8][4];
#pragma unroll
    for (int t = 0; t < 2; t++)
#pragma unroll
        for (int nt = 0; nt < 8; nt++)
#pragma unroll
            for (int j = 0; j < 4; j++) c[t][nt][j] = 0.f;

#pragma unroll
    for (int ks = 0; ks < 8; ks++) {
        unsigned a[2][4];
        ldsm4(a[0][0], a[0][1], a[0][2], a[0][3], aaddr0 + ks * 32);
        ldsm4(a[1][0], a[1][1], a[1][2], a[1][3], aaddr0 + 16 * ROWB + ks * 32);
#pragma unroll
        for (int nt = 0; nt < 8; nt++) {
            unsigned b0, b1;
            ldsm2(b0, b1, baddr0 + nt * 8 * ROWB + ks * 32);
            mma_f16(c[0][nt], a[0], b0, b1);
            mma_f16(c[1][nt], a[1], b0, b1);
        }
    }

    float ps0[2] = {0.f, 0.f}, ps1[2] = {0.f, 0.f};
    float pd0[2] = {0.f, 0.f}, pd1[2] = {0.f, 0.f};
#pragma unroll
    for (int t = 0; t < 2; t++) {
#pragma unroll
        for (int nt = 0; nt < 8; nt++) {
            int col = warp_n * 64 + nt * 8 + tg * 2;
            float a0 = sAS[col], a1 = sAS[col + 1];
            float d0 = sAD[col], d1 = sAD[col + 1];
            ps0[t] += c[t][nt][0] * a0 + c[t][nt][1] * a1;
            ps1[t] += c[t][nt][2] * a0 + c[t][nt][3] * a1;
            pd0[t] += c[t][nt][0] * d0 + c[t][nt][1] * d1;
            pd1[t] += c[t][nt][2] * d0 + c[t][nt][3] * d1;
        }
    }

    __syncthreads();   // ldmatrix reads done -> reuse A buffer for C

#pragma unroll
    for (int t = 0; t < 2; t++) {
        int r0 = warp_m * 32 + t * 16 + g;
        int cb = warp_n * 32;
#pragma unroll
        for (int nt = 0; nt < 8; nt++) {
            int cw = cb + nt * 4 + tg;
            Cs[r0 * 68 + cw] = packh2(c[t][nt][0], c[t][nt][1]);
            Cs[(r0 + 8) * 68 + cw] = packh2(c[t][nt][2], c[t][nt][3]);
        }
    }

#pragma unroll
    for (int t = 0; t < 2; t++) {
#pragma unroll
        for (int o = 1; o < 4; o <<= 1) {
            ps0[t] += __shfl_xor_sync(0xFFFFFFFFu, ps0[t], o);
            ps1[t] += __shfl_xor_sync(0xFFFFFFFFu, ps1[t], o);
            pd0[t] += __shfl_xor_sync(0xFFFFFFFFu, pd0[t], o);
            pd1[t] += __shfl_xor_sync(0xFFFFFFFFu, pd1[t], o);
        }
        if (tg == 0) {
            int lr = warp_m * 32 + t * 16 + g;
            red[warp_n * 128 + lr] = ps0[t];
            red[warp_n * 128 + lr + 8] = ps1[t];
            red[256 + warp_n * 128 + lr] = pd0[t];
            red[256 + warp_n * 128 + lr + 8] = pd1[t];
        }
    }
    __syncthreads();

    for (int i = tid; i < 2048; i += 256) {
        int r = i >> 4, cc = i & 15;
        int gr = row_blk + r;
        if (gr < NN) {
            uint4 v = *(uint4*)((char*)Cs + r * ROWB + cc * 16);
            *(uint4*)((char*)g_hp16 + (size_t)gr * 256 + cc * 16) = v;
        }
    }
    if (tid < 128) {
        int gr = row_blk + tid;
        if (gr < NN) {
            g_s[gr] = red[tid] + red[128 + tid];
            g_d[gr] = red[256 + tid] + red[384 + tid];
        }
    }
}

// ---------------- warp-per-node single-pass softmax + fp16 gather -------------
__global__ __launch_bounds__(256) void agg_k(
    const float* __restrict__ b, float* __restrict__ out,
    int layer, int colbase, int writeH) {
    __shared__ float sw[8][32];
    __shared__ int   ssrc[8][32];
    int warp = (blockIdx.x * blockDim.x + threadIdx.x) >> 5;  // exact: NN warps
    int lane = threadIdx.x & 31;
    int ws = (threadIdx.x >> 5) & 7;
    int n = warp;
    int beg = g_off[n], end = g_off[n + 1];
    float c = g_scal[1 + layer];
    float dterm = g_d[n];

    float4 acc = make_float4(0.f, 0.f, 0.f, 0.f);
    float denom = 0.f;
    for (int i0 = beg; i0 < end; i0 += 32) {
        int i = i0 + lane;
        int src = 0; float w = 0.f;
        if (i < end) {
            uint2 p = g_epack[i];
            src = (int)p.x;
            float a = g_s[src] + dterm + c * __uint_as_float(p.y);
            a = (a > 0.f) ? a : NEG * a;
            w = __expf(a);            // softmax shift-invariant; alpha is O(10)
            denom += w;
        }
        sw[ws][lane] = w;
        ssrc[ws][lane] = src;
        __syncwarp();
        int nvalid = min(32, end - i0);
#pragma unroll 4
        for (int j = 0; j < nvalid; j++) {
            float wj = sw[ws][j];
            uint2 p = g_hp16[ssrc[ws][j] * 32 + lane];
            float2 lo = __half22float2(*(__half2*)&p.x);
            float2 hi = __half22float2(*(__half2*)&p.y);
            acc.x += wj * lo.x;
            acc.y += wj * lo.y;
            acc.z += wj * hi.x;
            acc.w += wj * hi.y;
        }
        __syncwarp();
    }
#pragma unroll
    for (int o = 16; o; o >>= 1) denom += __shfl_xor_sync(0xFFFFFFFFu, denom, o);

    float inv = 1.0f / (denom + 1e-16f);
    float bx = b[lane * 4 + 0], by = b[lane * 4 + 1],
          bz = b[lane * 4 + 2], bw = b[lane * 4 + 3];
    float4 o4;
    o4.x = fmaxf(acc.x * inv + bx, 0.f);
    o4.y = fmaxf(acc.y * inv + by, 0.f);
    o4.z = fmaxf(acc.z * inv + bz, 0.f);
    o4.w = fmaxf(acc.w * inv + bw, 0.f);
    *(float4*)&out[n * 384 + colbase + lane * 4] = o4;
    if (writeH)
        g_a16[n * 32 + lane] = make_uint2(packh2(o4.x, o4.y), packh2(o4.z, o4.w));
}

extern "C" void kernel_launch(void* const* d_in, const int* in_sizes, int n_in,
                              void* d_out, int out_size) {
    const float* x   = (const float*)d_in[0];
    const int*   ei  = (const int*)d_in[1];     // int32 [2, E]
    const float* ea  = (const float*)d_in[2];
    const float* W0  = (const float*)d_in[3];
    const float* as0 = (const float*)d_in[4];
    const float* ad0 = (const float*)d_in[5];
    const float* We0 = (const float*)d_in[6];
    const float* ae0 = (const float*)d_in[7];
    const float* b0  = (const float*)d_in[8];
    const float* W1  = (const float*)d_in[9];
    const float* as1 = (const float*)d_in[10];
    const float* ad1 = (const float*)d_in[11];
    const float* We1 = (const float*)d_in[12];
    const float* ae1 = (const float*)d_in[13];
    const float* b1  = (const float*)d_in[14];
    float* out = (float*)d_out;

    cudaFuncSetAttribute(gemm_tc_k, cudaFuncAttributeMaxDynamicSharedMemorySize,
                         SMEM_GEMM);

    // one-time side stream + events (host objects only; no device allocations)
    static cudaStream_t s2 = nullptr;
    static cudaEvent_t evFork = nullptr, evJoin = nullptr;
    if (s2 == nullptr) {
        cudaStreamCreateWithFlags(&s2, cudaStreamNonBlocking);
        cudaEventCreateWithFlags(&evFork, cudaEventDisableTiming);
        cudaEventCreateWithFlags(&evJoin, cudaEventDisableTiming);
    }

    const int T = 256;
    const int blkN32 = (NN * 32) / T;                   // 6250
    const int blkN   = (NN + T - 1) / T;                // 196
    const int blkE2  = ((EE + NN + 1) / 2 + T - 1) / T;
    const int blkG   = (NN + 127) / 128;                // 391

    // fork: branch B (s2) = conv + gemm0 ; branch A (main) = CSR chain
    cudaEventRecord(evFork, 0);
    cudaStreamWaitEvent(s2, evFork, 0);

    // branch B on s2
    conv_k<<<NB_X + 32, T, 0, s2>>>((const float4*)x, out,
                                    (const float4*)W0, (const float4*)W1);
    gemm_tc_k<<<blkG, T, SMEM_GEMM, s2>>>(0, as0, ad0);
    cudaEventRecord(evJoin, s2);

    // branch A on main (capture) stream
    pre_csr_k<<<196 + 256, T>>>(ea);
    count_setup_k<<<NB_CNT + 1, T>>>(ei, We0, ae0, We1, ae1);
    scan1_k<<<blkN, T>>>();
    scan3_k<<<blkN, T>>>();
    scatter_k<<<blkE2, T>>>(ei, ea);

    // join, then the serial tail
    cudaStreamWaitEvent(0, evJoin, 0);
    agg_k<<<blkN32, T>>>(b0, out, 0, 128, 1);
    gemm_tc_k<<<blkG, T, SMEM_GEMM>>>(1, as1, ad1);
    agg_k<<<blkN32, T>>>(b1, out, 1, 256, 0);
}

// round 15
// speedup vs baseline: 1.0043x; 1.0043x over previous
#include <cuda_runtime.h>
#include <cuda_fp16.h>
#include <cuda_bf16.h>

#define NN 50000
#define EE 600000
#define HH 128
#define NEG 0.2f

// ---------------- device scratch (no allocs allowed) ----------------
__device__ uint2  g_hp16[NN * 32];    // h @ W^T in fp16 (4 vals per uint2)
__device__ uint2  g_a16[NN * 32];     // GEMM A operand in fp16 (x, then layer-1 out)
__device__ uint2  g_w16[2][4096];     // W0/W1 in fp16 ([c][k] row-major)
__device__ float  g_s[NN];            // hp . att_src
__device__ float  g_d[NN];            // hp . att_dst
__device__ int    g_cnt[NN];          // degree counts, then scatter cursors
__device__ int    g_off[NN + 1];      // CSR offsets by destination (real edges only)
__device__ uint2  g_epack[EE];        // CSR slot: {src, bitcast(edge_attr)}
__device__ float  g_scal[4];          // [0]=mean(edge_attr) [1]=c0 [2]=c1
__device__ float  g_partial[256];     // mean reduction partials
__device__ int    g_blksum[256];      // scan block partials

// ---------------- helpers ----------------
__device__ __forceinline__ unsigned packh2(float a, float b) {
    __half2 h = __floats2half2_rn(a, b);
    return *reinterpret_cast<unsigned*>(&h);
}

__device__ __forceinline__ void mma_f16(float* c, const unsigned* a,
                                        unsigned b0, unsigned b1) {
    asm volatile(
        "mma.sync.aligned.m16n8k16.row.col.f32.f16.f16.f32 "
        "{%0,%1,%2,%3}, {%4,%5,%6,%7}, {%8,%9}, {%0,%1,%2,%3};"
        : "+f"(c[0]), "+f"(c[1]), "+f"(c[2]), "+f"(c[3])
        : "r"(a[0]), "r"(a[1]), "r"(a[2]), "r"(a[3]), "r"(b0), "r"(b1));
}

__device__ __forceinline__ void ldsm4(unsigned& a0, unsigned& a1,
                                      unsigned& a2, unsigned& a3, unsigned addr) {
    asm volatile("ldmatrix.sync.aligned.m8n8.x4.shared.b16 {%0,%1,%2,%3}, [%4];"
                 : "=r"(a0), "=r"(a1), "=r"(a2), "=r"(a3) : "r"(addr));
}

__device__ __forceinline__ void ldsm2(unsigned& a0, unsigned& a1, unsigned addr) {
    asm volatile("ldmatrix.sync.aligned.m8n8.x2.shared.b16 {%0,%1}, [%2];"
                 : "=r"(a0), "=r"(a1) : "r"(addr));
}

// ---------------- conv: x conv + W conv + mean partials (branch B) ------------
#define NB_X ((NN * 32) / 256)          // 6250
#define NB_CONV (NB_X + 32 + 256)
__global__ void conv_k(const float4* __restrict__ x4, float* __restrict__ out,
                       const float4* __restrict__ W0_4,
                       const float4* __restrict__ W1_4,
                       const float* __restrict__ ea) {
    int bid = blockIdx.x;
    int t = threadIdx.x;
    if (bid < NB_X) {
        int i = bid * 256 + t;
        float4 v = x4[i];
        int n = i >> 5, q = i & 31;
        *(float4*)&out[n * 384 + q * 4] = v;
        g_a16[i] = make_uint2(packh2(v.x, v.y), packh2(v.z, v.w));
    } else if (bid < NB_X + 32) {
        int j = (bid - NB_X) * 256 + t;
        int mat = j >> 12, idx = j & 4095;
        float4 v = mat ? W1_4[idx] : W0_4[idx];
        g_w16[mat][idx] = make_uint2(packh2(v.x, v.y), packh2(v.z, v.w));
    } else {
        __shared__ float sm[256];
        int mb = bid - (NB_X + 32);
        float sum = 0.f;
        for (int i = mb * 256 + t; i < EE; i += 256 * 256) sum += ea[i];
        sm[t] = sum;
        __syncthreads();
        for (int o = 128; o; o >>= 1) {
            if (t < o) sm[t] += sm[t + o];
            __syncthreads();
        }
        if (t == 0) g_partial[mb] = sm[0];
    }
}

// ---------------- scalar setup (branch B, 1 block) ----------------------------
__global__ void setup_k(const float* __restrict__ We0, const float* __restrict__ ae0,
                        const float* __restrict__ We1, const float* __restrict__ ae1) {
    __shared__ float sm[256];
    int t = threadIdx.x;
    sm[t] = g_partial[t];
    __syncthreads();
    for (int o = 128; o; o >>= 1) {
        if (t < o) sm[t] += sm[t + o];
        __syncthreads();
    }
    if (t == 0) g_scal[0] = sm[0] / (float)EE;
    __syncthreads();
    sm[t] = (t < HH) ? We0[t] * ae0[t] : 0.f;
    __syncthreads();
    for (int o = 128; o; o >>= 1) {
        if (t < o) sm[t] += sm[t + o];
        __syncthreads();
    }
    if (t == 0) g_scal[1] = sm[0];
    __syncthreads();
    sm[t] = (t < HH) ? We1[t] * ae1[t] : 0.f;
    __syncthreads();
    for (int o = 128; o; o >>= 1) {
        if (t < o) sm[t] += sm[t + o];
        __syncthreads();
    }
    if (t == 0) g_scal[2] = sm[0];
}

// ---------------- CSR build (branch A; real edges only) -----------------------
__global__ void init0_k() {
    int i = blockIdx.x * blockDim.x + threadIdx.x;
    if (i < NN) g_cnt[i] = 0;
}

#define NB_CNT ((EE / 4 + 255) / 256)   // 586
__global__ void count_k(const int* __restrict__ ei) {
    int e4 = (blockIdx.x * 256 + threadIdx.x) * 4;
    if (e4 >= EE) return;
    int4 d = *(const int4*)&ei[EE + e4];    // EE % 4 == 0
    atomicAdd(&g_cnt[d.x], 1);
    atomicAdd(&g_cnt[d.y], 1);
    atomicAdd(&g_cnt[d.z], 1);
    atomicAdd(&g_cnt[d.w], 1);
}

__global__ void scan1_k() {
    __shared__ int sm[256];
    int t = threadIdx.x;
    int gi = blockIdx.x * 256 + t;
    int v = (gi < NN) ? g_cnt[gi] : 0;
    sm[t] = v;
    __syncthreads();
    for (int o = 1; o < 256; o <<= 1) {
        int add = (t >= o) ? sm[t - o] : 0;
        __syncthreads();
        sm[t] += add;
        __syncthreads();
    }
    if (gi < NN) g_off[gi] = sm[t] - v;
    if (t == 255) g_blksum[blockIdx.x] = sm[255];
}

__global__ void scan3_k() {
    __shared__ int sm[256];
    int t = threadIdx.x;
    sm[t] = (t < (int)blockIdx.x) ? g_blksum[t] : 0;
    __syncthreads();
    for (int o = 128; o; o >>= 1) {
        if (t < o) sm[t] += sm[t + o];
        __syncthreads();
    }
    int base = sm[0];
    int gi = blockIdx.x * 256 + t;
    if (gi < NN) {
        int off = g_off[gi] + base;
        g_off[gi] = off;
        g_cnt[gi] = off;
    }
    if (gi == 0) g_off[NN] = EE;
}

__global__ void scatter_k(const int* __restrict__ ei,
                          const float* __restrict__ eattr) {
    int e2 = (blockIdx.x * blockDim.x + threadIdx.x) * 2;
    if (e2 >= EE) return;                    // EE % 2 == 0
    int2 s = *(const int2*)&ei[e2];
    int2 d = *(const int2*)&ei[EE + e2];
    float2 a = *(const float2*)&eattr[e2];
    int p0 = atomicAdd(&g_cnt[d.x], 1);
    g_epack[p0] = make_uint2((unsigned)s.x, __float_as_uint(a.x));
    int p1 = atomicAdd(&g_cnt[d.y], 1);
    g_epack[p1] = make_uint2((unsigned)s.y, __float_as_uint(a.y));
}

// ---------------- fp16 GEMM: 1 tile/block, smem-transposed epilogue -----------
#define ROWB 272
#define TILEB (128 * ROWB)
#define SMEM_GEMM (2 * TILEB + 512 * 4 + 256 * 4)
__global__ __launch_bounds__(256) void gemm_tc_k(
    int layer, const float* __restrict__ as, const float* __restrict__ ad) {
    extern __shared__ char smem[];
    unsigned sW = (unsigned)__cvta_generic_to_shared(smem);
    unsigned sA = sW + TILEB;
    unsigned* Cs = (unsigned*)(smem + TILEB);          // C reuses A buffer
    float* red = (float*)(smem + 2 * TILEB);           // 512 floats
    float* sAS = red + 512;                            // 128 floats
    float* sAD = sAS + 128;                            // 128 floats

    const __half* __restrict__ A16 = (const __half*)g_a16;
    const __half* __restrict__ W16 = (const __half*)g_w16[layer];

    int tid = threadIdx.x;
    int wid = tid >> 5, lane = tid & 31;
    int warp_m = wid >> 1;
    int warp_n = wid & 1;
    int g = lane >> 2;
    int tg = lane & 3;
    int row_blk = blockIdx.x * 128;

    for (int i = tid; i < 2048; i += 256) {
        int r = i >> 4, cc = i & 15;
        asm volatile("cp.async.ca.shared.global [%0], [%1], 16, 16;"
                     :: "r"(sW + r * ROWB + cc * 16),
                        "l"(W16 + r * 128 + cc * 8));
    }
    for (int i = tid; i < 2048; i += 256) {
        int r = i >> 4, cc = i & 15;
        int gr = row_blk + r;
        const __half* src = A16 + (size_t)(gr < NN ? gr : 0) * 128 + cc * 8;
        int sz = (gr < NN) ? 16 : 0;
        asm volatile("cp.async.ca.shared.global [%0], [%1], 16, %2;"
                     :: "r"(sA + r * ROWB + cc * 16), "l"(src), "r"(sz));
    }
    asm volatile("cp.async.commit_group;");
    if (tid < 128) sAS[tid] = as[tid];
    else           sAD[tid - 128] = ad[tid - 128];
    asm volatile("cp.async.wait_group 0;");
    __syncthreads();

    int sel = lane >> 3, lrow = lane & 7;
    int arow0 = warp_m * 32 + lrow + ((sel & 1) ? 8 : 0);
    unsigned aaddr0 = sA + arow0 * ROWB + ((sel & 2) ? 16 : 0);
    unsigned baddr0 = sW + (warp_n * 64 + (lane & 7)) * ROWB + ((sel & 1) ? 16 : 0);

    float c[2][8][4];
#pragma unroll
    for (int t = 0; t < 2; t++)
#pragma unroll
        for (int nt = 0; nt < 8; nt++)
#pragma unroll
            for (int j = 0; j < 4; j++) c[t][nt][j] = 0.f;

#pragma unroll
    for (int ks = 0; ks < 8; ks++) {
        unsigned a[2][4];
        ldsm4(a[0][0], a[0][1], a[0][2], a[0][3], aaddr0 + ks * 32);
        ldsm4(a[1][0], a[1][1], a[1][2], a[1][3], aaddr0 + 16 * ROWB + ks * 32);
#pragma unroll
        for (int nt = 0; nt < 8; nt++) {
            unsigned b0, b1;
            ldsm2(b0, b1, baddr0 + nt * 8 * ROWB + ks * 32);
            mma_f16(c[0][nt], a[0], b0, b1);
            mma_f16(c[1][nt], a[1], b0, b1);
        }
    }

    float ps0[2] = {0.f, 0.f}, ps1[2] = {0.f, 0.f};
    float pd0[2] = {0.f, 0.f}, pd1[2] = {0.f, 0.f};
#pragma unroll
    for (int t = 0; t < 2; t++) {
#pragma unroll
        for (int nt = 0; nt < 8; nt++) {
            int col = warp_n * 64 + nt * 8 + tg * 2;
            float a0 = sAS[col], a1 = sAS[col + 1];
            float d0 = sAD[col], d1 = sAD[col + 1];
            ps0[t] += c[t][nt][0] * a0 + c[t][nt][1] * a1;
            ps1[t] += c[t][nt][2] * a0 + c[t][nt][3] * a1;
            pd0[t] += c[t][nt][0] * d0 + c[t][nt][1] * d1;
            pd1[t] += c[t][nt][2] * d0 + c[t][nt][3] * d1;
        }
    }

    __syncthreads();   // ldmatrix reads done -> reuse A buffer for C

#pragma unroll
    for (int t = 0; t < 2; t++) {
        int r0 = warp_m * 32 + t * 16 + g;
        int cb = warp_n * 32;
#pragma unroll
        for (int nt = 0; nt < 8; nt++) {
            int cw = cb + nt * 4 + tg;
            Cs[r0 * 68 + cw] = packh2(c[t][nt][0], c[t][nt][1]);
            Cs[(r0 + 8) * 68 + cw] = packh2(c[t][nt][2], c[t][nt][3]);
        }
    }

#pragma unroll
    for (int t = 0; t < 2; t++) {
#pragma unroll
        for (int o = 1; o < 4; o <<= 1) {
            ps0[t] += __shfl_xor_sync(0xFFFFFFFFu, ps0[t], o);
            ps1[t] += __shfl_xor_sync(0xFFFFFFFFu, ps1[t], o);
            pd0[t] += __shfl_xor_sync(0xFFFFFFFFu, pd0[t], o);
            pd1[t] += __shfl_xor_sync(0xFFFFFFFFu, pd1[t], o);
        }
        if (tg == 0) {
            int lr = warp_m * 32 + t * 16 + g;
            red[warp_n * 128 + lr] = ps0[t];
            red[warp_n * 128 + lr + 8] = ps1[t];
            red[256 + warp_n * 128 + lr] = pd0[t];
            red[256 + warp_n * 128 + lr + 8] = pd1[t];
        }
    }
    __syncthreads();

    for (int i = tid; i < 2048; i += 256) {
        int r = i >> 4, cc = i & 15;
        int gr = row_blk + r;
        if (gr < NN) {
            uint4 v = *(uint4*)((char*)Cs + r * ROWB + cc * 16);
            *(uint4*)((char*)g_hp16 + (size_t)gr * 256 + cc * 16) = v;
        }
    }
    if (tid < 128) {
        int gr = row_blk + tid;
        if (gr < NN) {
            g_s[gr] = red[tid] + red[128 + tid];
            g_d[gr] = red[256 + tid] + red[384 + tid];
        }
    }
}

// ---------------- warp-per-node softmax + gather (self-loop inline) -----------
__global__ __launch_bounds__(256) void agg_k(
    const float* __restrict__ b, float* __restrict__ out,
    int layer, int colbase, int writeH) {
    __shared__ float sw[8][32];
    __shared__ int   ssrc[8][32];
    int warp = (blockIdx.x * blockDim.x + threadIdx.x) >> 5;  // exact: NN warps
    int lane = threadIdx.x & 31;
    int ws = (threadIdx.x >> 5) & 7;
    int n = warp;
    int beg = g_off[n], end = g_off[n + 1];
    float c = g_scal[1 + layer];
    float sterm = g_s[n];
    float dterm = g_d[n];

    // self loop: src = dst = n, ea = mean(edge_attr)
    float aS = sterm + dterm + c * g_scal[0];
    aS = (aS > 0.f) ? aS : NEG * aS;
    float wSelf = __expf(aS);

    float4 acc;
    {
        uint2 p = g_hp16[n * 32 + lane];
        float2 lo = __half22float2(*(__half2*)&p.x);
        float2 hi = __half22float2(*(__half2*)&p.y);
        acc = make_float4(wSelf * lo.x, wSelf * lo.y, wSelf * hi.x, wSelf * hi.y);
    }
    float denom = 0.f;
    for (int i0 = beg; i0 < end; i0 += 32) {
        int i = i0 + lane;
        int src = 0; float w = 0.f;
        if (i < end) {
            uint2 p = g_epack[i];
            src = (int)p.x;
            float a = g_s[src] + dterm + c * __uint_as_float(p.y);
            a = (a > 0.f) ? a : NEG * a;
            w = __expf(a);            // softmax shift-invariant; alpha is O(10)
            denom += w;
        }
        sw[ws][lane] = w;
        ssrc[ws][lane] = src;
        __syncwarp();
        int nvalid = min(32, end - i0);
#pragma unroll 4
        for (int j = 0; j < nvalid; j++) {
            float wj = sw[ws][j];
            uint2 p = g_hp16[ssrc[ws][j] * 32 + lane];
            float2 lo = __half22float2(*(__half2*)&p.x);
            float2 hi = __half22float2(*(__half2*)&p.y);
            acc.x += wj * lo.x;
            acc.y += wj * lo.y;
            acc.z += wj * hi.x;
            acc.w += wj * hi.y;
        }
        __syncwarp();
    }
#pragma unroll
    for (int o = 16; o; o >>= 1) denom += __shfl_xor_sync(0xFFFFFFFFu, denom, o);
    denom += wSelf;

    float inv = 1.0f / (denom + 1e-16f);
    float bx = b[lane * 4 + 0], by = b[lane * 4 + 1],
          bz = b[lane * 4 + 2], bw = b[lane * 4 + 3];
    float4 o4;
    o4.x = fmaxf(acc.x * inv + bx, 0.f);
    o4.y = fmaxf(acc.y * inv + by, 0.f);
    o4.z = fmaxf(acc.z * inv + bz, 0.f);
    o4.w = fmaxf(acc.w * inv + bw, 0.f);
    *(float4*)&out[n * 384 + colbase + lane * 4] = o4;
    if (writeH)
        g_a16[n * 32 + lane] = make_uint2(packh2(o4.x, o4.y), packh2(o4.z, o4.w));
}

extern "C" void kernel_launch(void* const* d_in, const int* in_sizes, int n_in,
                              void* d_out, int out_size) {
    const float* x   = (const float*)d_in[0];
    const int*   ei  = (const int*)d_in[1];     // int32 [2, E]
    const float* ea  = (const float*)d_in[2];
    const float* W0  = (const float*)d_in[3];
    const float* as0 = (const float*)d_in[4];
    const float* ad0 = (const float*)d_in[5];
    const float* We0 = (const float*)d_in[6];
    const float* ae0 = (const float*)d_in[7];
    const float* b0  = (const float*)d_in[8];
    const float* W1  = (const float*)d_in[9];
    const float* as1 = (const float*)d_in[10];
    const float* ad1 = (const float*)d_in[11];
    const float* We1 = (const float*)d_in[12];
    const float* ae1 = (const float*)d_in[13];
    const float* b1  = (const float*)d_in[14];
    float* out = (float*)d_out;

    cudaFuncSetAttribute(gemm_tc_k, cudaFuncAttributeMaxDynamicSharedMemorySize,
                         SMEM_GEMM);

    // one-time side stream + events (host objects only; no device allocations)
    static cudaStream_t s2 = nullptr;
    static cudaEvent_t evFork = nullptr, evJoin = nullptr;
    if (s2 == nullptr) {
        cudaStreamCreateWithFlags(&s2, cudaStreamNonBlocking);
        cudaEventCreateWithFlags(&evFork, cudaEventDisableTiming);
        cudaEventCreateWithFlags(&evJoin, cudaEventDisableTiming);
    }

    const int T = 256;
    const int blkN32 = (NN * 32) / T;                   // 6250
    const int blkN   = (NN + T - 1) / T;                // 196
    const int blkE2  = (EE / 2 + T - 1) / T;            // 1172
    const int blkG   = (NN + 127) / 128;                // 391

    // fork: branch B (s2) = conv+scalars+gemm0 ; branch A (main) = CSR chain
    cudaEventRecord(evFork, 0);
    cudaStreamWaitEvent(s2, evFork, 0);

    // branch B on s2
    conv_k<<<NB_CONV, T, 0, s2>>>((const float4*)x, out,
                                  (const float4*)W0, (const float4*)W1, ea);
    setup_k<<<1, T, 0, s2>>>(We0, ae0, We1, ae1);
    gemm_tc_k<<<blkG, T, SMEM_GEMM, s2>>>(0, as0, ad0);
    cudaEventRecord(evJoin, s2);

    // branch A on main (capture) stream — no dependency on mean/scalars
    init0_k<<<blkN, T>>>();
    count_k<<<NB_CNT, T>>>(ei);
    scan1_k<<<blkN, T>>>();
    scan3_k<<<blkN, T>>>();
    scatter_k<<<blkE2, T>>>(ei, ea);

    // join, then the serial tail
    cudaStreamWaitEvent(0, evJoin, 0);
    agg_k<<<blkN32, T>>>(b0, out, 0, 128, 1);
    gemm_tc_k<<<blkG, T, SMEM_GEMM>>>(1, as1, ad1);
    agg_k<<<blkN32, T>>>(b1, out, 1, 256, 0);
}